// round 6
// baseline (speedup 1.0000x reference)
#include <cuda_runtime.h>
#include <math.h>

#define BB 2048
#define NN 100
#define GG 100
#define EE 128
#define NT 1024

// smem regions (floats)
#define SA_OFF   0        // enc -> last -> mask(flat 10000)
#define SK_OFF   13200    // k -> mh
#define SV_OFF   26400    // mean scratch -> v -> encT[128][100]
#define SQ_OFF   39600    // q -> attn -> S[100][104]
#define SG_OFF   52800    // graph mean [128]
#define SQG_OFF  52928    // q_graph [128]
#define SMEM_FLOATS 53056

typedef unsigned long long ull;

__device__ __forceinline__ ull bcast2(float a) {
    ull r; asm("mov.b64 %0, {%1,%1};" : "=l"(r) : "f"(a)); return r;
}
__device__ __forceinline__ ull ffma2(ull a, ull b, ull c) {
    ull d; asm("fma.rn.f32x2 %0, %1, %2, %3;" : "=l"(d) : "l"(a), "l"(b), "l"(c));
    return d;
}
__device__ __forceinline__ float4 unpack4(ull a, ull b) {
    float4 r;
    asm("mov.b64 {%0,%1}, %2;" : "=f"(r.x), "=f"(r.y) : "l"(a));
    asm("mov.b64 {%0,%1}, %2;" : "=f"(r.z), "=f"(r.w) : "l"(b));
    return r;
}
__device__ __forceinline__ float tanh_acc(float x) {
    float ax = fabsf(x);
    float e = __expf(-2.0f * ax);
    float t = __fdividef(1.0f - e, 1.0f + e);
    return copysignf(t, x);
}

__device__ float g_Wfl[EE * 128];

__global__ void prep_kernel(const float* __restrict__ Wqf,
                            const float* __restrict__ Wql) {
    int i = blockIdx.x * blockDim.x + threadIdx.x;
    if (i < EE * 128) g_Wfl[i] = Wqf[i] + Wql[i];
}

// 8-row x 4-col tile: A rows from smem (stride lda), W [128][128] row-major global.
__device__ __forceinline__ void gemm8(const float* sBase, int r0, int lda,
                                      const float* __restrict__ W, int j0,
                                      ull acc[8][2]) {
    int off[8];
    #pragma unroll
    for (int i = 0; i < 8; ++i) off[i] = min(r0 + i, NN - 1) * lda;
    #pragma unroll
    for (int i = 0; i < 8; ++i) { acc[i][0] = 0ULL; acc[i][1] = 0ULL; }
    #pragma unroll 4
    for (int e = 0; e < EE; ++e) {
        const ulonglong2 w2 = *reinterpret_cast<const ulonglong2*>(W + e * 128 + j0);
        #pragma unroll
        for (int i = 0; i < 8; ++i) {
            ull ap = bcast2(sBase[off[i] + e]);
            acc[i][0] = ffma2(ap, w2.x, acc[i][0]);
            acc[i][1] = ffma2(ap, w2.y, acc[i][1]);
        }
    }
}

__global__ __launch_bounds__(NT, 1)
void pomo_decoder_kernel(const float* __restrict__ enc,
                         const float* __restrict__ last,
                         const float* __restrict__ mask,
                         const float* __restrict__ Wqg,
                         const float* __restrict__ Wk,
                         const float* __restrict__ Wv,
                         const float* __restrict__ Wc,
                         const float* __restrict__ bc,
                         float* __restrict__ out) {
    extern __shared__ float sm[];
    float* sA  = sm + SA_OFF;
    float* sK  = sm + SK_OFF;
    float* sV  = sm + SV_OFF;
    float* sQ  = sm + SQ_OFF;
    float* sG  = sm + SG_OFF;
    float* sQg = sm + SQG_OFF;

    const int b    = blockIdx.x;
    const int tid  = threadIdx.x;
    const int lane = tid & 31;
    const int warp = tid >> 5;   // 0..31
    const int j0   = lane * 4;

    const float* encB  = enc  + (size_t)b * NN * EE;
    const float* lastB = last + (size_t)b * GG * EE;
    const float* maskB = mask + (size_t)b * GG * NN;
    float*       outB  = out  + (size_t)b * GG * NN;

    // A: enc -> sA
    for (int idx = tid; idx < NN * 32; idx += NT) {
        int n = idx >> 5, e4 = (idx & 31) * 4;
        *reinterpret_cast<float4*>(sA + n * 132 + e4) =
            *reinterpret_cast<const float4*>(encB + n * EE + e4);
    }
    __syncthreads();

    // graph mean: 8 partials per e into sV scratch
    {
        int part = tid >> 7, e = tid & 127;
        int rb = part * 13, re = min(rb + 13, NN);
        float s = 0.f;
        for (int n = rb; n < re; ++n) s += sA[n * 132 + e];
        sV[part * 128 + e] = s;
    }
    __syncthreads();
    if (tid < EE) {
        float s = 0.f;
        #pragma unroll
        for (int p = 0; p < 8; ++p) s += sV[p * 128 + tid];
        sG[tid] = s * (1.0f / NN);
    }
    __syncthreads();

    // B: k (warps 0-12), v (warps 13-25), q_graph (warps 26-29)
    if (warp < 13) {
        ull acc[8][2];
        const int r0 = warp * 8;
        gemm8(sA, r0, 132, Wk, j0, acc);
        #pragma unroll
        for (int i = 0; i < 8; ++i)
            if (r0 + i < NN)
                *reinterpret_cast<float4*>(sK + (r0 + i) * 132 + j0) =
                    unpack4(acc[i][0], acc[i][1]);
    } else if (warp < 26) {
        ull acc[8][2];
        const int r0 = (warp - 13) * 8;
        gemm8(sA, r0, 132, Wv, j0, acc);
        #pragma unroll
        for (int i = 0; i < 8; ++i)
            if (r0 + i < NN)
                *reinterpret_cast<float4*>(sV + (r0 + i) * 132 + j0) =
                    unpack4(acc[i][0], acc[i][1]);
    } else if (warp < 30) {
        int j = (warp - 26) * 32 + lane;
        float s = 0.f;
        #pragma unroll 4
        for (int e = 0; e < EE; ++e) s += sG[e] * Wqg[e * 128 + j];
        sQg[j] = s;
    }
    __syncthreads();

    // C: last -> sA
    for (int idx = tid; idx < GG * 32; idx += NT) {
        int g = idx >> 5, e4 = (idx & 31) * 4;
        *reinterpret_cast<float4*>(sA + g * 132 + e4) =
            *reinterpret_cast<const float4*>(lastB + g * EE + e4);
    }
    __syncthreads();

    // q = qg + last @ (Wqf+Wql)  (warps 0-12)
    if (warp < 13) {
        ull acc[8][2];
        const int r0 = warp * 8;
        gemm8(sA, r0, 132, g_Wfl, j0, acc);
        const float4 qg4 = *reinterpret_cast<const float4*>(sQg + j0);
        #pragma unroll
        for (int i = 0; i < 8; ++i)
            if (r0 + i < GG) {
                float4 r = unpack4(acc[i][0], acc[i][1]);
                r.x += qg4.x; r.y += qg4.y; r.z += qg4.z; r.w += qg4.w;
                *reinterpret_cast<float4*>(sQ + (r0 + i) * 132 + j0) = r;
            }
    }
    __syncthreads();

    // stage mask -> sA (flat [g*100+n])
    for (int idx = tid; idx < (GG * NN) / 4; idx += NT)
        reinterpret_cast<float4*>(sA)[idx] =
            reinterpret_cast<const float4*>(maskB)[idx];
    __syncthreads();

    // D: attention, one (g,h) per thread; attn overwrites q in sQ
    {
        const int g = tid & 127;
        const int h = tid >> 7;     // 0..7
        if (g < GG) {
            const int c0 = h * 16;
            float q[16], acc[16];
            #pragma unroll
            for (int d = 0; d < 16; ++d) { q[d] = sQ[g * 132 + c0 + d]; acc[d] = 0.f; }
            float m = -1e30f, l = 0.f;
            const float* mrow = sA + g * NN;
            for (int n = 0; n < NN; ++n) {
                const float* kr = sK + n * 132 + c0;
                float s = 0.f;
                #pragma unroll
                for (int d = 0; d < 16; ++d) s += q[d] * kr[d];
                s = s * 0.25f + mrow[n];
                const float mn = fmaxf(m, s);
                const float c  = __expf(m - mn);
                const float p  = __expf(s - mn);
                l = l * c + p;
                const float* vr = sV + n * 132 + c0;
                #pragma unroll
                for (int d = 0; d < 16; ++d) acc[d] = acc[d] * c + p * vr[d];
                m = mn;
            }
            const float rl = __fdividef(1.f, l);
            #pragma unroll
            for (int d = 0; d < 16; ++d) sQ[g * 132 + c0 + d] = acc[d] * rl;
        }
    }
    __syncthreads();

    // E: mh = attn @ Wc + bc -> sK (warps 0-12) || encT -> sV (warps 13-31)
    if (warp < 13) {
        ull acc[8][2];
        const int r0 = warp * 8;
        gemm8(sQ, r0, 132, Wc, j0, acc);
        const float4 b4 = *reinterpret_cast<const float4*>(bc + j0);
        #pragma unroll
        for (int i = 0; i < 8; ++i)
            if (r0 + i < GG) {
                float4 r = unpack4(acc[i][0], acc[i][1]);
                r.x += b4.x; r.y += b4.y; r.z += b4.z; r.w += b4.w;
                *reinterpret_cast<float4*>(sK + (r0 + i) * 132 + j0) = r;
            }
    } else {
        for (int idx = tid - 13 * 32; idx < NN * 32; idx += NT - 13 * 32) {
            int n = idx >> 5, e4 = (idx & 31) * 4;
            float4 v = *reinterpret_cast<const float4*>(encB + n * EE + e4);
            sV[(e4 + 0) * 100 + n] = v.x;
            sV[(e4 + 1) * 100 + n] = v.y;
            sV[(e4 + 2) * 100 + n] = v.z;
            sV[(e4 + 3) * 100 + n] = v.w;
        }
    }
    __syncthreads();

    // F1: S = 10*tanh((mh @ encT)/sqrt(128)) -> sQ stride 104 (warps 0-12)
    if (warp < 13 && lane < 25) {
        const int n0 = j0;          // lane*4, < 100
        const int r0 = warp * 8;
        int off[8];
        #pragma unroll
        for (int i = 0; i < 8; ++i) off[i] = min(r0 + i, NN - 1) * 132;
        ull acc[8][2];
        #pragma unroll
        for (int i = 0; i < 8; ++i) { acc[i][0] = 0ULL; acc[i][1] = 0ULL; }
        #pragma unroll 4
        for (int e = 0; e < EE; ++e) {
            const ulonglong2 b2 = *reinterpret_cast<const ulonglong2*>(sV + e * 100 + n0);
            #pragma unroll
            for (int i = 0; i < 8; ++i) {
                ull ap = bcast2(sK[off[i] + e]);
                acc[i][0] = ffma2(ap, b2.x, acc[i][0]);
                acc[i][1] = ffma2(ap, b2.y, acc[i][1]);
            }
        }
        const float rsE = 0.08838834764831845f;
        #pragma unroll
        for (int i = 0; i < 8; ++i)
            if (r0 + i < GG) {
                float4 r = unpack4(acc[i][0], acc[i][1]);
                r.x = 10.f * tanh_acc(r.x * rsE);
                r.y = 10.f * tanh_acc(r.y * rsE);
                r.z = 10.f * tanh_acc(r.z * rsE);
                r.w = 10.f * tanh_acc(r.w * rsE);
                *reinterpret_cast<float4*>(sQ + (r0 + i) * 104 + n0) = r;
            }
    }
    __syncthreads();

    // F2: masked softmax per row -> out  (mask from sA)
    for (int g = warp; g < GG; g += 32) {
        float v[4];
        float mx = -1e30f;
        #pragma unroll
        for (int r = 0; r < 4; ++r) {
            const int n = lane + r * 32;
            float x = -1e30f;
            if (n < NN) x = sQ[g * 104 + n] + sA[g * NN + n];
            v[r] = x;
            mx = fmaxf(mx, x);
        }
        #pragma unroll
        for (int o = 16; o > 0; o >>= 1) mx = fmaxf(mx, __shfl_xor_sync(~0u, mx, o));
        float sum = 0.f;
        #pragma unroll
        for (int r = 0; r < 4; ++r) {
            const int n = lane + r * 32;
            float e = (n < NN) ? __expf(v[r] - mx) : 0.f;
            v[r] = e;
            sum += e;
        }
        #pragma unroll
        for (int o = 16; o > 0; o >>= 1) sum += __shfl_xor_sync(~0u, sum, o);
        const float inv = __fdividef(1.f, sum);
        #pragma unroll
        for (int r = 0; r < 4; ++r) {
            const int n = lane + r * 32;
            if (n < NN) outB[g * NN + n] = v[r] * inv;
        }
    }
}

extern "C" void kernel_launch(void* const* d_in, const int* in_sizes, int n_in,
                              void* d_out, int out_size) {
    const float* enc  = (const float*)d_in[0];
    const float* last = (const float*)d_in[1];
    const float* mask = (const float*)d_in[2];
    const float* Wqg  = (const float*)d_in[3];
    const float* Wqf  = (const float*)d_in[4];
    const float* Wql  = (const float*)d_in[5];
    const float* Wk   = (const float*)d_in[6];
    const float* Wv   = (const float*)d_in[7];
    const float* Wc   = (const float*)d_in[8];
    const float* bc   = (const float*)d_in[9];
    float* out = (float*)d_out;

    prep_kernel<<<(EE * 128 + 255) / 256, 256>>>(Wqf, Wql);

    const size_t smem_bytes = (size_t)SMEM_FLOATS * sizeof(float);
    cudaFuncSetAttribute(pomo_decoder_kernel,
                         cudaFuncAttributeMaxDynamicSharedMemorySize,
                         (int)smem_bytes);
    pomo_decoder_kernel<<<BB, NT, smem_bytes>>>(enc, last, mask, Wqg,
                                                Wk, Wv, Wc, bc, out);
}

// round 8
// speedup vs baseline: 1.0013x; 1.0013x over previous
#include <cuda_runtime.h>
#include <math.h>

#define BB 2048
#define NN 100
#define GG 100
#define EE 128
#define NT 1024

// smem regions (floats)
#define SA_OFF   0        // enc -> last -> mask(flat 10000)
#define SK_OFF   13200    // k -> mh
#define SV_OFF   26400    // mean scratch -> v -> encT[128][100]
#define SQ_OFF   39600    // q -> attn -> S[100][104]
#define SG_OFF   52800    // graph mean [128]
#define SQG_OFF  52928    // q_graph [128]
#define SMEM_FLOATS 53056

typedef unsigned long long ull;

__device__ __forceinline__ ull bcast2(float a) {
    ull r; asm("mov.b64 %0, {%1,%1};" : "=l"(r) : "f"(a)); return r;
}
__device__ __forceinline__ ull ffma2(ull a, ull b, ull c) {
    ull d; asm("fma.rn.f32x2 %0, %1, %2, %3;" : "=l"(d) : "l"(a), "l"(b), "l"(c));
    return d;
}
__device__ __forceinline__ float4 unpack4(ull a, ull b) {
    float4 r;
    asm("mov.b64 {%0,%1}, %2;" : "=f"(r.x), "=f"(r.y) : "l"(a));
    asm("mov.b64 {%0,%1}, %2;" : "=f"(r.z), "=f"(r.w) : "l"(b));
    return r;
}
__device__ __forceinline__ float tanh_acc(float x) {
    float ax = fabsf(x);
    float e = __expf(-2.0f * ax);
    float t = __fdividef(1.0f - e, 1.0f + e);
    return copysignf(t, x);
}

__device__ float g_Wfl[EE * 128];

__global__ void prep_kernel(const float* __restrict__ Wqf,
                            const float* __restrict__ Wql) {
    int i = blockIdx.x * blockDim.x + threadIdx.x;
    if (i < EE * 128) g_Wfl[i] = Wqf[i] + Wql[i];
}

// 8-row x 4-col tile: A rows from smem (stride lda), W [128][128] row-major global.
__device__ __forceinline__ void gemm8(const float* sBase, int r0, int lda,
                                      const float* __restrict__ W, int j0,
                                      ull acc[8][2]) {
    int off[8];
    #pragma unroll
    for (int i = 0; i < 8; ++i) off[i] = min(r0 + i, NN - 1) * lda;
    #pragma unroll
    for (int i = 0; i < 8; ++i) { acc[i][0] = 0ULL; acc[i][1] = 0ULL; }
    #pragma unroll 4
    for (int e = 0; e < EE; ++e) {
        const ulonglong2 w2 = *reinterpret_cast<const ulonglong2*>(W + e * 128 + j0);
        #pragma unroll
        for (int i = 0; i < 8; ++i) {
            ull ap = bcast2(sBase[off[i] + e]);
            acc[i][0] = ffma2(ap, w2.x, acc[i][0]);
            acc[i][1] = ffma2(ap, w2.y, acc[i][1]);
        }
    }
}

__global__ __launch_bounds__(NT, 1)
void pomo_decoder_kernel(const float* __restrict__ enc,
                         const float* __restrict__ last,
                         const float* __restrict__ mask,
                         const float* __restrict__ Wqg,
                         const float* __restrict__ Wk,
                         const float* __restrict__ Wv,
                         const float* __restrict__ Wc,
                         const float* __restrict__ bc,
                         float* __restrict__ out) {
    extern __shared__ float sm[];
    float* sA  = sm + SA_OFF;
    float* sK  = sm + SK_OFF;
    float* sV  = sm + SV_OFF;
    float* sQ  = sm + SQ_OFF;
    float* sG  = sm + SG_OFF;
    float* sQg = sm + SQG_OFF;

    const int b    = blockIdx.x;
    const int tid  = threadIdx.x;
    const int lane = tid & 31;
    const int warp = tid >> 5;   // 0..31
    const int j0   = lane * 4;

    const float* encB  = enc  + (size_t)b * NN * EE;
    const float* lastB = last + (size_t)b * GG * EE;
    const float* maskB = mask + (size_t)b * GG * NN;
    float*       outB  = out  + (size_t)b * GG * NN;

    // A: enc -> sA
    for (int idx = tid; idx < NN * 32; idx += NT) {
        int n = idx >> 5, e4 = (idx & 31) * 4;
        *reinterpret_cast<float4*>(sA + n * 132 + e4) =
            *reinterpret_cast<const float4*>(encB + n * EE + e4);
    }
    __syncthreads();

    // graph mean: 8 partials per e into sV scratch
    {
        int part = tid >> 7, e = tid & 127;
        int rb = part * 13, re = min(rb + 13, NN);
        float s = 0.f;
        for (int n = rb; n < re; ++n) s += sA[n * 132 + e];
        sV[part * 128 + e] = s;
    }
    __syncthreads();
    if (tid < EE) {
        float s = 0.f;
        #pragma unroll
        for (int p = 0; p < 8; ++p) s += sV[p * 128 + tid];
        sG[tid] = s * (1.0f / NN);
    }
    __syncthreads();

    // B: k (warps 0-12), v (warps 13-25), q_graph (warps 26-29)
    if (warp < 13) {
        ull acc[8][2];
        const int r0 = warp * 8;
        gemm8(sA, r0, 132, Wk, j0, acc);
        #pragma unroll
        for (int i = 0; i < 8; ++i)
            if (r0 + i < NN)
                *reinterpret_cast<float4*>(sK + (r0 + i) * 132 + j0) =
                    unpack4(acc[i][0], acc[i][1]);
    } else if (warp < 26) {
        ull acc[8][2];
        const int r0 = (warp - 13) * 8;
        gemm8(sA, r0, 132, Wv, j0, acc);
        #pragma unroll
        for (int i = 0; i < 8; ++i)
            if (r0 + i < NN)
                *reinterpret_cast<float4*>(sV + (r0 + i) * 132 + j0) =
                    unpack4(acc[i][0], acc[i][1]);
    } else if (warp < 30) {
        int j = (warp - 26) * 32 + lane;
        float s = 0.f;
        #pragma unroll 4
        for (int e = 0; e < EE; ++e) s += sG[e] * Wqg[e * 128 + j];
        sQg[j] = s;
    }
    __syncthreads();

    // C: last -> sA
    for (int idx = tid; idx < GG * 32; idx += NT) {
        int g = idx >> 5, e4 = (idx & 31) * 4;
        *reinterpret_cast<float4*>(sA + g * 132 + e4) =
            *reinterpret_cast<const float4*>(lastB + g * EE + e4);
    }
    __syncthreads();

    // q = qg + last @ (Wqf+Wql)  (warps 0-12)
    if (warp < 13) {
        ull acc[8][2];
        const int r0 = warp * 8;
        gemm8(sA, r0, 132, g_Wfl, j0, acc);
        const float4 qg4 = *reinterpret_cast<const float4*>(sQg + j0);
        #pragma unroll
        for (int i = 0; i < 8; ++i)
            if (r0 + i < GG) {
                float4 r = unpack4(acc[i][0], acc[i][1]);
                r.x += qg4.x; r.y += qg4.y; r.z += qg4.z; r.w += qg4.w;
                *reinterpret_cast<float4*>(sQ + (r0 + i) * 132 + j0) = r;
            }
    }
    __syncthreads();

    // stage mask -> sA (flat [g*100+n])
    for (int idx = tid; idx < (GG * NN) / 4; idx += NT)
        reinterpret_cast<float4*>(sA)[idx] =
            reinterpret_cast<const float4*>(maskB)[idx];
    __syncthreads();

    // D: attention, one (g,h) per thread; attn overwrites q in sQ
    {
        const int g = tid & 127;
        const int h = tid >> 7;     // 0..7
        if (g < GG) {
            const int c0 = h * 16;
            float q[16], acc[16];
            #pragma unroll
            for (int d = 0; d < 16; ++d) { q[d] = sQ[g * 132 + c0 + d]; acc[d] = 0.f; }
            float m = -1e30f, l = 0.f;
            const float* mrow = sA + g * NN;
            for (int n = 0; n < NN; ++n) {
                const float* kr = sK + n * 132 + c0;
                float s = 0.f;
                #pragma unroll
                for (int d = 0; d < 16; ++d) s += q[d] * kr[d];
                s = s * 0.25f + mrow[n];
                const float mn = fmaxf(m, s);
                const float c  = __expf(m - mn);
                const float p  = __expf(s - mn);
                l = l * c + p;
                const float* vr = sV + n * 132 + c0;
                #pragma unroll
                for (int d = 0; d < 16; ++d) acc[d] = acc[d] * c + p * vr[d];
                m = mn;
            }
            const float rl = __fdividef(1.f, l);
            #pragma unroll
            for (int d = 0; d < 16; ++d) sQ[g * 132 + c0 + d] = acc[d] * rl;
        }
    }
    __syncthreads();

    // E: mh = attn @ Wc + bc -> sK (warps 0-12) || encT -> sV (warps 13-31)
    if (warp < 13) {
        ull acc[8][2];
        const int r0 = warp * 8;
        gemm8(sQ, r0, 132, Wc, j0, acc);
        const float4 b4 = *reinterpret_cast<const float4*>(bc + j0);
        #pragma unroll
        for (int i = 0; i < 8; ++i)
            if (r0 + i < GG) {
                float4 r = unpack4(acc[i][0], acc[i][1]);
                r.x += b4.x; r.y += b4.y; r.z += b4.z; r.w += b4.w;
                *reinterpret_cast<float4*>(sK + (r0 + i) * 132 + j0) = r;
            }
    } else {
        for (int idx = tid - 13 * 32; idx < NN * 32; idx += NT - 13 * 32) {
            int n = idx >> 5, e4 = (idx & 31) * 4;
            float4 v = *reinterpret_cast<const float4*>(encB + n * EE + e4);
            sV[(e4 + 0) * 100 + n] = v.x;
            sV[(e4 + 1) * 100 + n] = v.y;
            sV[(e4 + 2) * 100 + n] = v.z;
            sV[(e4 + 3) * 100 + n] = v.w;
        }
    }
    __syncthreads();

    // F1: S = 10*tanh((mh @ encT)/sqrt(128)) -> sQ stride 104 (warps 0-12)
    if (warp < 13 && lane < 25) {
        const int n0 = j0;          // lane*4, < 100
        const int r0 = warp * 8;
        int off[8];
        #pragma unroll
        for (int i = 0; i < 8; ++i) off[i] = min(r0 + i, NN - 1) * 132;
        ull acc[8][2];
        #pragma unroll
        for (int i = 0; i < 8; ++i) { acc[i][0] = 0ULL; acc[i][1] = 0ULL; }
        #pragma unroll 4
        for (int e = 0; e < EE; ++e) {
            const ulonglong2 b2 = *reinterpret_cast<const ulonglong2*>(sV + e * 100 + n0);
            #pragma unroll
            for (int i = 0; i < 8; ++i) {
                ull ap = bcast2(sK[off[i] + e]);
                acc[i][0] = ffma2(ap, b2.x, acc[i][0]);
                acc[i][1] = ffma2(ap, b2.y, acc[i][1]);
            }
        }
        const float rsE = 0.08838834764831845f;
        #pragma unroll
        for (int i = 0; i < 8; ++i)
            if (r0 + i < GG) {
                float4 r = unpack4(acc[i][0], acc[i][1]);
                r.x = 10.f * tanh_acc(r.x * rsE);
                r.y = 10.f * tanh_acc(r.y * rsE);
                r.z = 10.f * tanh_acc(r.z * rsE);
                r.w = 10.f * tanh_acc(r.w * rsE);
                *reinterpret_cast<float4*>(sQ + (r0 + i) * 104 + n0) = r;
            }
    }
    __syncthreads();

    // F2: masked softmax per row -> out  (mask from sA)
    for (int g = warp; g < GG; g += 32) {
        float v[4];
        float mx = -1e30f;
        #pragma unroll
        for (int r = 0; r < 4; ++r) {
            const int n = lane + r * 32;
            float x = -1e30f;
            if (n < NN) x = sQ[g * 104 + n] + sA[g * NN + n];
            v[r] = x;
            mx = fmaxf(mx, x);
        }
        #pragma unroll
        for (int o = 16; o > 0; o >>= 1) mx = fmaxf(mx, __shfl_xor_sync(~0u, mx, o));
        float sum = 0.f;
        #pragma unroll
        for (int r = 0; r < 4; ++r) {
            const int n = lane + r * 32;
            float e = (n < NN) ? __expf(v[r] - mx) : 0.f;
            v[r] = e;
            sum += e;
        }
        #pragma unroll
        for (int o = 16; o > 0; o >>= 1) sum += __shfl_xor_sync(~0u, sum, o);
        const float inv = __fdividef(1.f, sum);
        #pragma unroll
        for (int r = 0; r < 4; ++r) {
            const int n = lane + r * 32;
            if (n < NN) outB[g * NN + n] = v[r] * inv;
        }
    }
}

extern "C" void kernel_launch(void* const* d_in, const int* in_sizes, int n_in,
                              void* d_out, int out_size) {
    const float* enc  = (const float*)d_in[0];
    const float* last = (const float*)d_in[1];
    const float* mask = (const float*)d_in[2];
    const float* Wqg  = (const float*)d_in[3];
    const float* Wqf  = (const float*)d_in[4];
    const float* Wql  = (const float*)d_in[5];
    const float* Wk   = (const float*)d_in[6];
    const float* Wv   = (const float*)d_in[7];
    const float* Wc   = (const float*)d_in[8];
    const float* bc   = (const float*)d_in[9];
    float* out = (float*)d_out;

    prep_kernel<<<(EE * 128 + 255) / 256, 256>>>(Wqf, Wql);

    const size_t smem_bytes = (size_t)SMEM_FLOATS * sizeof(float);
    cudaFuncSetAttribute(pomo_decoder_kernel,
                         cudaFuncAttributeMaxDynamicSharedMemorySize,
                         (int)smem_bytes);
    pomo_decoder_kernel<<<BB, NT, smem_bytes>>>(enc, last, mask, Wqg,
                                                Wk, Wv, Wc, bc, out);
}

// round 10
// speedup vs baseline: 1.3321x; 1.3304x over previous
#include <cuda_runtime.h>
#include <math.h>

#define BB 2048
#define NN 100
#define GG 100
#define EE 128
#define NT 1024

// smem float offsets
#define SE_OFF   0        // encT[128][104] -> lastT[128][104] -> maskT[100][100]
#define SK_OFF   13312    // k[100][132] -> mhT[128][100]
#define SV_OFF   26512    // v[100][132] -> encT2[128][100]
#define SQ_OFF   39712    // q[100][132] -> attnT[128][100] -> S[100][104]
#define SCR_OFF  52912    // mean scratch 1024
#define SG_OFF   53936    // 128
#define SQG_OFF  54064    // 128
#define SMEM_FLOATS 54192

typedef unsigned long long ull;

__device__ __forceinline__ ull bcast2(float a) {
    ull r; asm("mov.b64 %0, {%1,%1};" : "=l"(r) : "f"(a)); return r;
}
__device__ __forceinline__ ull pack2(float lo, float hi) {
    ull r; asm("mov.b64 %0, {%1,%2};" : "=l"(r) : "f"(lo), "f"(hi)); return r;
}
__device__ __forceinline__ void unpack2(ull v, float& lo, float& hi) {
    asm("mov.b64 {%0,%1}, %2;" : "=f"(lo), "=f"(hi) : "l"(v));
}
__device__ __forceinline__ ull ffma2(ull a, ull b, ull c) {
    ull d; asm("fma.rn.f32x2 %0, %1, %2, %3;" : "=l"(d) : "l"(a), "l"(b), "l"(c));
    return d;
}
__device__ __forceinline__ float tanh_acc(float x) {
    float ax = fabsf(x);
    float e = __expf(-2.0f * ax);
    float t = __fdividef(1.0f - e, 1.0f + e);
    return copysignf(t, x);
}

__device__ float g_Wfl[EE * 128];

__global__ void prep_kernel(const float* __restrict__ Wqf,
                            const float* __restrict__ Wql) {
    int i = blockIdx.x * blockDim.x + threadIdx.x;
    if (i < EE * 128) g_Wfl[i] = Wqf[i] + Wql[i];
}

__global__ __launch_bounds__(NT, 1)
void pomo_decoder_kernel(const float* __restrict__ enc,
                         const float* __restrict__ last,
                         const float* __restrict__ mask,
                         const float* __restrict__ Wqg,
                         const float* __restrict__ Wk,
                         const float* __restrict__ Wv,
                         const float* __restrict__ Wc,
                         const float* __restrict__ bc,
                         float* __restrict__ out) {
    extern __shared__ float sm[];
    float* sE  = sm + SE_OFF;    // encT -> lastT -> maskT
    float* sK  = sm + SK_OFF;    // k rows -> mhT
    float* sV  = sm + SV_OFF;    // v rows -> encT2
    float* sQ  = sm + SQ_OFF;    // q rows -> attnT -> S
    float* sCR = sm + SCR_OFF;
    float* sG  = sm + SG_OFF;
    float* sQg = sm + SQG_OFF;

    const int b    = blockIdx.x;
    const int tid  = threadIdx.x;
    const int lane = tid & 31;
    const int warp = tid >> 5;   // 0..31

    const float* encB  = enc  + (size_t)b * NN * EE;
    const float* lastB = last + (size_t)b * GG * EE;
    const float* maskB = mask + (size_t)b * GG * NN;
    float*       outB  = out  + (size_t)b * GG * NN;

    // ---- A: enc -> encT[e][n] (stride 104) --------------------------------
    for (int idx = tid; idx < NN * 32; idx += NT) {
        int n = idx >> 5, e4 = (idx & 31) * 4;
        float4 v = *reinterpret_cast<const float4*>(encB + n * EE + e4);
        sE[(e4 + 0) * 104 + n] = v.x;
        sE[(e4 + 1) * 104 + n] = v.y;
        sE[(e4 + 2) * 104 + n] = v.z;
        sE[(e4 + 3) * 104 + n] = v.w;
    }
    __syncthreads();

    // mean partials over n (contiguous in encT rows)
    {
        int p = tid >> 7, e = tid & 127;
        int nb = p * 13, ne = min(nb + 13, NN);
        float s = 0.f;
        for (int n = nb; n < ne; ++n) s += sE[e * 104 + n];
        sCR[p * 128 + e] = s;
    }
    __syncthreads();
    if (tid < EE) {
        float s = 0.f;
        #pragma unroll
        for (int p = 0; p < 8; ++p) s += sCR[p * 128 + tid];
        sG[tid] = s * (1.0f / NN);
    }
    __syncthreads();

    // ---- B: k (warps 0-12) / v (warps 13-25) / qg (warps 26-29) -----------
    if (warp < 26) {
        const float* W = (warp < 13) ? Wk : Wv;
        float* dst     = (warp < 13) ? sK : sV;
        const int n0   = (warp < 13 ? warp : warp - 13) * 8;
        const int j0   = lane * 4;
        ull acc[4][4];
        #pragma unroll
        for (int i = 0; i < 4; ++i)
            #pragma unroll
            for (int c = 0; c < 4; ++c) acc[i][c] = 0ULL;
        #pragma unroll 2
        for (int e = 0; e < EE; ++e) {
            const float* er = sE + e * 104 + n0;
            ull a0 = *reinterpret_cast<const ull*>(er + 0);
            ull a1 = *reinterpret_cast<const ull*>(er + 2);
            ull a2 = *reinterpret_cast<const ull*>(er + 4);
            ull a3 = *reinterpret_cast<const ull*>(er + 6);
            float4 w4 = *reinterpret_cast<const float4*>(W + e * 128 + j0);
            ull w0 = bcast2(w4.x), w1 = bcast2(w4.y);
            ull w2 = bcast2(w4.z), w3 = bcast2(w4.w);
            acc[0][0] = ffma2(a0, w0, acc[0][0]); acc[0][1] = ffma2(a0, w1, acc[0][1]);
            acc[0][2] = ffma2(a0, w2, acc[0][2]); acc[0][3] = ffma2(a0, w3, acc[0][3]);
            acc[1][0] = ffma2(a1, w0, acc[1][0]); acc[1][1] = ffma2(a1, w1, acc[1][1]);
            acc[1][2] = ffma2(a1, w2, acc[1][2]); acc[1][3] = ffma2(a1, w3, acc[1][3]);
            acc[2][0] = ffma2(a2, w0, acc[2][0]); acc[2][1] = ffma2(a2, w1, acc[2][1]);
            acc[2][2] = ffma2(a2, w2, acc[2][2]); acc[2][3] = ffma2(a2, w3, acc[2][3]);
            acc[3][0] = ffma2(a3, w0, acc[3][0]); acc[3][1] = ffma2(a3, w1, acc[3][1]);
            acc[3][2] = ffma2(a3, w2, acc[3][2]); acc[3][3] = ffma2(a3, w3, acc[3][3]);
        }
        #pragma unroll
        for (int i = 0; i < 4; ++i) {
            int r = n0 + 2 * i;
            if (r < NN) {
                #pragma unroll
                for (int c = 0; c < 4; ++c) {
                    float lo, hi; unpack2(acc[i][c], lo, hi);
                    dst[r * 132 + j0 + c] = lo;
                    dst[(r + 1) * 132 + j0 + c] = hi;   // r+1 <= 99 when r<100 (r even)
                }
            }
        }
    } else if (warp < 30) {
        int j = (warp - 26) * 32 + lane;
        float s = 0.f;
        #pragma unroll 4
        for (int e = 0; e < EE; ++e) s += sG[e] * Wqg[e * 128 + j];
        sQg[j] = s;
    }
    __syncthreads();

    // ---- C stage: last -> lastT (sE) ---------------------------------------
    for (int idx = tid; idx < GG * 32; idx += NT) {
        int g = idx >> 5, e4 = (idx & 31) * 4;
        float4 v = *reinterpret_cast<const float4*>(lastB + g * EE + e4);
        sE[(e4 + 0) * 104 + g] = v.x;
        sE[(e4 + 1) * 104 + g] = v.y;
        sE[(e4 + 2) * 104 + g] = v.z;
        sE[(e4 + 3) * 104 + g] = v.w;
    }
    __syncthreads();

    // ---- C: q = qg + lastT-pairs @ Wfl (26 warps, col halves) -> q rows ----
    if (warp < 26) {
        const int half = warp / 13, wr = warp % 13;
        const int g0 = wr * 8;
        const int j0 = half * 64 + lane * 2;
        ull acc[4][2];
        #pragma unroll
        for (int i = 0; i < 4; ++i) { acc[i][0] = 0ULL; acc[i][1] = 0ULL; }
        #pragma unroll 2
        for (int e = 0; e < EE; ++e) {
            const float* er = sE + e * 104 + g0;
            ull a0 = *reinterpret_cast<const ull*>(er + 0);
            ull a1 = *reinterpret_cast<const ull*>(er + 2);
            ull a2 = *reinterpret_cast<const ull*>(er + 4);
            ull a3 = *reinterpret_cast<const ull*>(er + 6);
            float2 wf = *reinterpret_cast<const float2*>(g_Wfl + e * 128 + j0);
            ull w0 = bcast2(wf.x), w1 = bcast2(wf.y);
            acc[0][0] = ffma2(a0, w0, acc[0][0]); acc[0][1] = ffma2(a0, w1, acc[0][1]);
            acc[1][0] = ffma2(a1, w0, acc[1][0]); acc[1][1] = ffma2(a1, w1, acc[1][1]);
            acc[2][0] = ffma2(a2, w0, acc[2][0]); acc[2][1] = ffma2(a2, w1, acc[2][1]);
            acc[3][0] = ffma2(a3, w0, acc[3][0]); acc[3][1] = ffma2(a3, w1, acc[3][1]);
        }
        float qg0 = sQg[j0], qg1 = sQg[j0 + 1];
        #pragma unroll
        for (int i = 0; i < 4; ++i) {
            int r = g0 + 2 * i;
            if (r < GG) {
                float lo, hi;
                unpack2(acc[i][0], lo, hi);
                sQ[r * 132 + j0] = lo + qg0; sQ[(r + 1) * 132 + j0] = hi + qg0;
                unpack2(acc[i][1], lo, hi);
                sQ[r * 132 + j0 + 1] = lo + qg1; sQ[(r + 1) * 132 + j0 + 1] = hi + qg1;
            }
        }
    }
    __syncthreads();

    // ---- D prologue: stage maskT[n][g] (sE); load q into regs --------------
    for (int idx = tid; idx < (GG * NN) / 4; idx += NT) {
        int g = idx / 25, n4 = (idx % 25) * 4;
        float4 mv = *reinterpret_cast<const float4*>(maskB + g * NN + n4);
        sE[(n4 + 0) * 100 + g] = mv.x;
        sE[(n4 + 1) * 100 + g] = mv.y;
        sE[(n4 + 2) * 100 + g] = mv.z;
        sE[(n4 + 3) * 100 + g] = mv.w;
    }
    const int g  = tid & 127;
    const int h  = tid >> 7;
    const int c0 = h * 16;
    const bool act = (g < GG);
    ull q2[8];
    if (act) {
        const ulonglong2* qp = reinterpret_cast<const ulonglong2*>(sQ + g * 132 + c0);
        ulonglong2 t0 = qp[0], t1 = qp[1], t2 = qp[2], t3 = qp[3];
        q2[0] = t0.x; q2[1] = t0.y; q2[2] = t1.x; q2[3] = t1.y;
        q2[4] = t2.x; q2[5] = t2.y; q2[6] = t3.x; q2[7] = t3.y;
    }
    __syncthreads();   // maskT ready; all q reads done before attnT overwrites

    // ---- D: attention; write attnT[d][g] (sQ region) ------------------------
    if (act) {
        ull acc2[8];
        #pragma unroll
        for (int j = 0; j < 8; ++j) acc2[j] = 0ULL;
        float m = -1e30f, l = 0.f;
        const float* kb = sK + c0;
        const float* vb = sV + c0;
        for (int n = 0; n < NN; ++n) {
            const ulonglong2* kp = reinterpret_cast<const ulonglong2*>(kb + n * 132);
            ulonglong2 k0 = kp[0], k1 = kp[1], k2 = kp[2], k3 = kp[3];
            ull sa = 0ULL, sb = 0ULL;
            sa = ffma2(q2[0], k0.x, sa); sb = ffma2(q2[1], k0.y, sb);
            sa = ffma2(q2[2], k1.x, sa); sb = ffma2(q2[3], k1.y, sb);
            sa = ffma2(q2[4], k2.x, sa); sb = ffma2(q2[5], k2.y, sb);
            sa = ffma2(q2[6], k3.x, sa); sb = ffma2(q2[7], k3.y, sb);
            float x0, x1, y0, y1;
            unpack2(sa, x0, x1); unpack2(sb, y0, y1);
            float s = ((x0 + y0) + (x1 + y1)) * 0.25f + sE[n * 100 + g];
            const ulonglong2* vp = reinterpret_cast<const ulonglong2*>(vb + n * 132);
            ulonglong2 v0 = vp[0], v1 = vp[1], v2 = vp[2], v3 = vp[3];
            if (s > m) {
                float c = __expf(m - s);
                l = l * c + 1.0f;
                ull cc = bcast2(c);
                acc2[0] = ffma2(acc2[0], cc, v0.x); acc2[1] = ffma2(acc2[1], cc, v0.y);
                acc2[2] = ffma2(acc2[2], cc, v1.x); acc2[3] = ffma2(acc2[3], cc, v1.y);
                acc2[4] = ffma2(acc2[4], cc, v2.x); acc2[5] = ffma2(acc2[5], cc, v2.y);
                acc2[6] = ffma2(acc2[6], cc, v3.x); acc2[7] = ffma2(acc2[7], cc, v3.y);
                m = s;
            } else {
                float p = __expf(s - m);
                l += p;
                ull pp = bcast2(p);
                acc2[0] = ffma2(v0.x, pp, acc2[0]); acc2[1] = ffma2(v0.y, pp, acc2[1]);
                acc2[2] = ffma2(v1.x, pp, acc2[2]); acc2[3] = ffma2(v1.y, pp, acc2[3]);
                acc2[4] = ffma2(v2.x, pp, acc2[4]); acc2[5] = ffma2(v2.y, pp, acc2[5]);
                acc2[6] = ffma2(v3.x, pp, acc2[6]); acc2[7] = ffma2(v3.y, pp, acc2[7]);
            }
        }
        const float rl = __fdividef(1.f, l);
        #pragma unroll
        for (int j = 0; j < 8; ++j) {
            float lo, hi; unpack2(acc2[j], lo, hi);
            sQ[(c0 + 2 * j + 0) * 100 + g] = lo * rl;
            sQ[(c0 + 2 * j + 1) * 100 + g] = hi * rl;
        }
    }
    __syncthreads();

    // ---- E: mhT = (attnT-pairs @ Wc + bc)^T (26 warps) || encT2 (warps 26-31)
    if (warp < 26) {
        const int half = warp / 13, wr = warp % 13;
        const int g0 = wr * 8;
        const int j0 = half * 64 + lane * 2;
        ull acc[4][2];
        #pragma unroll
        for (int i = 0; i < 4; ++i) { acc[i][0] = 0ULL; acc[i][1] = 0ULL; }
        #pragma unroll 2
        for (int e = 0; e < EE; ++e) {
            const float* er = sQ + e * 100 + g0;    // attnT
            ull a0 = *reinterpret_cast<const ull*>(er + 0);
            ull a1 = *reinterpret_cast<const ull*>(er + 2);
            ull a2 = *reinterpret_cast<const ull*>(er + 4);
            ull a3 = *reinterpret_cast<const ull*>(er + 6);
            float2 wf = *reinterpret_cast<const float2*>(Wc + e * 128 + j0);
            ull w0 = bcast2(wf.x), w1 = bcast2(wf.y);
            acc[0][0] = ffma2(a0, w0, acc[0][0]); acc[0][1] = ffma2(a0, w1, acc[0][1]);
            acc[1][0] = ffma2(a1, w0, acc[1][0]); acc[1][1] = ffma2(a1, w1, acc[1][1]);
            acc[2][0] = ffma2(a2, w0, acc[2][0]); acc[2][1] = ffma2(a2, w1, acc[2][1]);
            acc[3][0] = ffma2(a3, w0, acc[3][0]); acc[3][1] = ffma2(a3, w1, acc[3][1]);
        }
        float b0 = bc[j0], b1 = bc[j0 + 1];
        #pragma unroll
        for (int i = 0; i < 4; ++i) {
            int r = g0 + 2 * i;
            if (r < GG) {
                float lo, hi;
                unpack2(acc[i][0], lo, hi);
                *reinterpret_cast<ull*>(sK + (j0 + 0) * 100 + r) = pack2(lo + b0, hi + b0);
                unpack2(acc[i][1], lo, hi);
                *reinterpret_cast<ull*>(sK + (j0 + 1) * 100 + r) = pack2(lo + b1, hi + b1);
            }
        }
    } else {
        for (int idx = tid - 26 * 32; idx < NN * 32; idx += NT - 26 * 32) {
            int n = idx >> 5, e4 = (idx & 31) * 4;
            float4 v = *reinterpret_cast<const float4*>(encB + n * EE + e4);
            sV[(e4 + 0) * 100 + n] = v.x;
            sV[(e4 + 1) * 100 + n] = v.y;
            sV[(e4 + 2) * 100 + n] = v.z;
            sV[(e4 + 3) * 100 + n] = v.w;
        }
    }
    __syncthreads();

    // ---- F1: S = 10*tanh((mhT-pairs . encT2)/sqrt(128)) (25 warps) ---------
    if (warp < 25 && lane < 25) {
        const int g0 = warp * 4;
        const int n0 = lane * 4;
        ull acc[2][4];
        #pragma unroll
        for (int i = 0; i < 2; ++i)
            #pragma unroll
            for (int c = 0; c < 4; ++c) acc[i][c] = 0ULL;
        #pragma unroll 4
        for (int e = 0; e < EE; ++e) {
            ull a0 = *reinterpret_cast<const ull*>(sK + e * 100 + g0);      // mhT pairs
            ull a1 = *reinterpret_cast<const ull*>(sK + e * 100 + g0 + 2);
            float4 b4 = *reinterpret_cast<const float4*>(sV + e * 100 + n0); // encT2
            ull w0 = bcast2(b4.x), w1 = bcast2(b4.y);
            ull w2 = bcast2(b4.z), w3 = bcast2(b4.w);
            acc[0][0] = ffma2(a0, w0, acc[0][0]); acc[0][1] = ffma2(a0, w1, acc[0][1]);
            acc[0][2] = ffma2(a0, w2, acc[0][2]); acc[0][3] = ffma2(a0, w3, acc[0][3]);
            acc[1][0] = ffma2(a1, w0, acc[1][0]); acc[1][1] = ffma2(a1, w1, acc[1][1]);
            acc[1][2] = ffma2(a1, w2, acc[1][2]); acc[1][3] = ffma2(a1, w3, acc[1][3]);
        }
        const float rsE = 0.08838834764831845f;
        #pragma unroll
        for (int r = 0; r < 4; ++r) {
            float4 o;
            float lo, hi;
            unpack2(acc[r >> 1][0], lo, hi); o.x = 10.f * tanh_acc(((r & 1) ? hi : lo) * rsE);
            unpack2(acc[r >> 1][1], lo, hi); o.y = 10.f * tanh_acc(((r & 1) ? hi : lo) * rsE);
            unpack2(acc[r >> 1][2], lo, hi); o.z = 10.f * tanh_acc(((r & 1) ? hi : lo) * rsE);
            unpack2(acc[r >> 1][3], lo, hi); o.w = 10.f * tanh_acc(((r & 1) ? hi : lo) * rsE);
            *reinterpret_cast<float4*>(sQ + (g0 + r) * 104 + n0) = o;
        }
    }
    __syncthreads();

    // ---- F2: masked softmax per g row -> out (mask from maskT) -------------
    for (int gr = warp; gr < GG; gr += 32) {
        float v[4];
        float mx = -1e30f;
        #pragma unroll
        for (int r = 0; r < 4; ++r) {
            const int n = lane + r * 32;
            float x = -1e30f;
            if (n < NN) x = sQ[gr * 104 + n] + sE[n * 100 + gr];
            v[r] = x;
            mx = fmaxf(mx, x);
        }
        #pragma unroll
        for (int o = 16; o > 0; o >>= 1) mx = fmaxf(mx, __shfl_xor_sync(~0u, mx, o));
        float sum = 0.f;
        #pragma unroll
        for (int r = 0; r < 4; ++r) {
            const int n = lane + r * 32;
            float e = (n < NN) ? __expf(v[r] - mx) : 0.f;
            v[r] = e;
            sum += e;
        }
        #pragma unroll
        for (int o = 16; o > 0; o >>= 1) sum += __shfl_xor_sync(~0u, sum, o);
        const float inv = __fdividef(1.f, sum);
        #pragma unroll
        for (int r = 0; r < 4; ++r) {
            const int n = lane + r * 32;
            if (n < NN) outB[gr * NN + n] = v[r] * inv;
        }
    }
}

extern "C" void kernel_launch(void* const* d_in, const int* in_sizes, int n_in,
                              void* d_out, int out_size) {
    const float* enc  = (const float*)d_in[0];
    const float* last = (const float*)d_in[1];
    const float* mask = (const float*)d_in[2];
    const float* Wqg  = (const float*)d_in[3];
    const float* Wqf  = (const float*)d_in[4];
    const float* Wql  = (const float*)d_in[5];
    const float* Wk   = (const float*)d_in[6];
    const float* Wv   = (const float*)d_in[7];
    const float* Wc   = (const float*)d_in[8];
    const float* bc   = (const float*)d_in[9];
    float* out = (float*)d_out;

    prep_kernel<<<(EE * 128 + 255) / 256, 256>>>(Wqf, Wql);

    const size_t smem_bytes = (size_t)SMEM_FLOATS * sizeof(float);
    cudaFuncSetAttribute(pomo_decoder_kernel,
                         cudaFuncAttributeMaxDynamicSharedMemorySize,
                         (int)smem_bytes);
    pomo_decoder_kernel<<<BB, NT, smem_bytes>>>(enc, last, mask, Wqg,
                                                Wk, Wv, Wc, bc, out);
}